// round 7
// baseline (speedup 1.0000x reference)
#include <cuda_runtime.h>
#include <math.h>
#include <stdint.h>

#define BATCH   32
#define DMODEL  4096
#define NH      32
#define NKV     8
#define GSZ     4          // NH / NKV
#define HD      128
#define QKV_COLS 6144      // (NH + 2*NKV) * HD
#define PBLOCK  64
#define NBLK    64
#define SPLITS  8
#define SPLIT_LEN 512      // 4096 / SPLITS
#define NSUB    SPLITS     // per-CTA merged partials
#define KSPLIT  16
#define KCHUNK  256        // 4096 / KSPLIT

typedef unsigned long long u64;

// -------------------- packed f32x2 helpers (sm_100+) ------------------------
__device__ __forceinline__ u64 ffma2(u64 a, u64 b, u64 c) {
    u64 d;
    asm("fma.rn.f32x2 %0, %1, %2, %3;" : "=l"(d) : "l"(a), "l"(b), "l"(c));
    return d;
}
__device__ __forceinline__ u64 pack2(float lo, float hi) {
    u64 r;
    asm("mov.b64 %0, {%1, %2};" : "=l"(r) : "f"(lo), "f"(hi));
    return r;
}
__device__ __forceinline__ float2 unpack2(u64 v) {
    float2 f;
    asm("mov.b64 {%0, %1}, %2;" : "=f"(f.x), "=f"(f.y) : "l"(v));
    return f;
}
union F4 {
    float4 f4;
    struct { u64 lo, hi; } u;
};

// ------------------------------ scratch -------------------------------------
__device__ float g_qkv_part[KSPLIT][BATCH][QKV_COLS];   // 12.6 MB
__device__ float g_q[BATCH][NH][HD];                    // prescaled by 1/sqrt(HD)
__device__ float g_knew[BATCH][NKV][HD];
__device__ float g_vnew[BATCH][NKV][HD];
__device__ float g_po[BATCH][NKV][GSZ][NSUB][HD];       // 4.2 MB
__device__ float g_pm[BATCH][NKV][GSZ][NSUB];
__device__ float g_pl[BATCH][NKV][GSZ][NSUB];
__device__ float g_attn[BATCH][NH * HD];
__device__ float g_out_part[KSPLIT][BATCH][DMODEL];     // 8.4 MB

// --------------------- K-split 32-row GEMM:  part[s] = x_chunk @ w_chunk ----
__global__ __launch_bounds__(128) void gemm32(const float* __restrict__ x,
                                              const float* __restrict__ w,
                                              float* __restrict__ part,
                                              int ncols) {
    __shared__ float hs[BATCH][KCHUNK];                 // 32 KB
    const int col = blockIdx.x * 128 + threadIdx.x;
    const int k0  = blockIdx.y * KCHUNK;

    for (int i = threadIdx.x; i < BATCH * (KCHUNK / 4); i += 128) {
        int b  = i >> 6;
        int kk = i & 63;
        ((float4*)hs[b])[kk] = ((const float4*)(x + (size_t)b * DMODEL + k0))[kk];
    }
    __syncthreads();

    u64 acc2[BATCH];
#pragma unroll
    for (int b = 0; b < BATCH; b++) acc2[b] = 0ULL;

    const float* wp = w + (size_t)k0 * ncols + col;
#pragma unroll 4
    for (int k = 0; k < KCHUNK; k += 4) {
        float w0 = wp[(size_t)(k + 0) * ncols];
        float w1 = wp[(size_t)(k + 1) * ncols];
        float w2 = wp[(size_t)(k + 2) * ncols];
        float w3 = wp[(size_t)(k + 3) * ncols];
        u64 w01 = pack2(w0, w1);
        u64 w23 = pack2(w2, w3);
#pragma unroll
        for (int b = 0; b < BATCH; b++) {
            F4 h;
            h.f4 = *(const float4*)&hs[b][k];
            acc2[b] = ffma2(h.u.lo, w01, ffma2(h.u.hi, w23, acc2[b]));
        }
    }
    float* op = part + ((size_t)blockIdx.y * BATCH) * ncols + col;
#pragma unroll
    for (int b = 0; b < BATCH; b++) {
        float2 f = unpack2(acc2[b]);
        op[(size_t)b * ncols] = f.x + f.y;
    }
}

// ----------------- reduce k-splits of QKV + RoPE + split q/k/v --------------
__global__ __launch_bounds__(256) void rope_reduce(const int* __restrict__ pos_ids) {
    int idx = blockIdx.x * 256 + threadIdx.x;
    int j  = idx & 63;
    int hh = (idx >> 6) % 48;
    int b  = idx / (48 * 64);

    int c1 = hh * HD + j;
    int c2 = c1 + 64;
    float x1 = 0.f, x2 = 0.f;
#pragma unroll
    for (int s = 0; s < KSPLIT; s++) {
        x1 += g_qkv_part[s][b][c1];
        x2 += g_qkv_part[s][b][c2];
    }
    if (hh < 40) {
        float invf = exp2f(-(float)j * (19.931568569324174f / 64.f)); // 1e6^(-j/64)
        float ang  = (float)pos_ids[b] * invf;
        float c = cosf(ang), s = sinf(ang);
        float y1 = x1 * c - x2 * s;
        float y2 = x2 * c + x1 * s;
        if (hh < 32) {
            const float sc = 0.08838834764831845f;   // 1/sqrt(128)
            g_q[b][hh][j]      = y1 * sc;
            g_q[b][hh][j + 64] = y2 * sc;
        } else {
            g_knew[b][hh - 32][j]      = y1;
            g_knew[b][hh - 32][j + 64] = y2;
        }
    } else {
        g_vnew[b][hh - 40][j]      = x1;
        g_vnew[b][hh - 40][j + 64] = x2;
    }
}

// ------------- per-warp two-phase split-KV flash-decode ----------------------
// grid: (SPLITS, NKV, BATCH), block 256 (8 warps).
// Phase A: per-warp K stream (octet dot products), scores -> smem float4.
//          unroll 4 => 16 LDG.128 per batch in flight.
// Phase B: per-warp max + exp + l.
// Phase C: per-warp V stream, all 32 lanes on one position; unroll 16.
// Epilogue: one __syncthreads, smem flash-merge of the 8 warps -> 1 partial.
__global__ __launch_bounds__(256, 2) void attn_split(const float* __restrict__ kc,
                                                     const float* __restrict__ vc,
                                                     const int* __restrict__ btab,
                                                     const int* __restrict__ seqlens) {
    const int s   = blockIdx.x;
    const int kvh = blockIdx.y;
    const int b   = blockIdx.z;

    __shared__ float4 ps4[8][PBLOCK];       // 8 KB: per-warp scores/probs (g-packed)
    __shared__ float  red[8][GSZ][HD];      // 16 KB: per-warp V partials
    __shared__ float  sm_m[8][GSZ], sm_l[8][GSZ];

    const int t    = threadIdx.x;
    const int w    = t >> 5;
    const int lane = t & 31;
    const int kvlen  = seqlens[b];
    const int newpos = kvlen - 1;

    const int phys = btab[b * NBLK + s * 8 + w];
    const int lsub = lane >> 3;      // octet index (position group)
    const int dch  = lane & 7;       // 16-dim chunk within octet

    const float* kblock = kc + ((size_t)phys * PBLOCK) * NKV * HD + (size_t)kvh * HD;
    const float* vblock = vc + ((size_t)phys * PBLOCK) * NKV * HD + (size_t)kvh * HD;
    const int base = s * SPLIT_LEN + w * 64;

    float mloc[GSZ];
    // ---------------- phase A: scores -> smem ----------------
    {
        F4 qr[GSZ][4];
#pragma unroll
        for (int g = 0; g < GSZ; g++) {
            const float4* qp = (const float4*)&g_q[b][kvh * GSZ + g][0];
#pragma unroll
            for (int q = 0; q < 4; q++) qr[g][q].f4 = qp[dch * 4 + q];
        }
#pragma unroll
        for (int g = 0; g < GSZ; g++) mloc[g] = -1e30f;

#pragma unroll 4
        for (int i = 0; i < 16; i++) {
            const int slot = i * 4 + lsub;
            const int gl = base + slot;
            const float* kp = kblock + (size_t)slot * NKV * HD;
            if (gl == newpos) kp = &g_knew[b][kvh][0];

            F4 kv[4];
#pragma unroll
            for (int q = 0; q < 4; q++) kv[q].f4 = __ldcs(((const float4*)kp) + dch * 4 + q);

            float sg[GSZ];
#pragma unroll
            for (int g = 0; g < GSZ; g++) {
                u64 a2 = 0ULL;
#pragma unroll
                for (int q = 0; q < 4; q++) {
                    a2 = ffma2(qr[g][q].u.lo, kv[q].u.lo, a2);
                    a2 = ffma2(qr[g][q].u.hi, kv[q].u.hi, a2);
                }
                float2 f = unpack2(a2);
                sg[g] = f.x + f.y;
            }
#pragma unroll
            for (int off = 1; off < 8; off <<= 1)
#pragma unroll
                for (int g = 0; g < GSZ; g++)
                    sg[g] += __shfl_xor_sync(0xffffffff, sg[g], off);

            if (dch == 0) {
                const bool valid = gl < kvlen;
                float4 sv;
                sv.x = valid ? sg[0] : -1e30f;
                sv.y = valid ? sg[1] : -1e30f;
                sv.z = valid ? sg[2] : -1e30f;
                sv.w = valid ? sg[3] : -1e30f;
                ps4[w][slot] = sv;
                mloc[0] = fmaxf(mloc[0], sv.x);
                mloc[1] = fmaxf(mloc[1], sv.y);
                mloc[2] = fmaxf(mloc[2], sv.z);
                mloc[3] = fmaxf(mloc[3], sv.w);
            }
        }
#pragma unroll
        for (int off = 16; off >= 1; off >>= 1)
#pragma unroll
            for (int g = 0; g < GSZ; g++)
                mloc[g] = fmaxf(mloc[g], __shfl_xor_sync(0xffffffff, mloc[g], off));
        __syncwarp();
    }

    // ---------------- phase B: exp + l ----------------
    {
        float4 s0 = ps4[w][lane];
        float4 s1 = ps4[w][lane + 32];
        float4 p0, p1;
        p0.x = __expf(s0.x - mloc[0]); p1.x = __expf(s1.x - mloc[0]);
        p0.y = __expf(s0.y - mloc[1]); p1.y = __expf(s1.y - mloc[1]);
        p0.z = __expf(s0.z - mloc[2]); p1.z = __expf(s1.z - mloc[2]);
        p0.w = __expf(s0.w - mloc[3]); p1.w = __expf(s1.w - mloc[3]);
        ps4[w][lane] = p0;
        ps4[w][lane + 32] = p1;
        float l0 = p0.x + p1.x, l1 = p0.y + p1.y;
        float l2 = p0.z + p1.z, l3 = p0.w + p1.w;
#pragma unroll
        for (int off = 16; off >= 1; off >>= 1) {
            l0 += __shfl_xor_sync(0xffffffff, l0, off);
            l1 += __shfl_xor_sync(0xffffffff, l1, off);
            l2 += __shfl_xor_sync(0xffffffff, l2, off);
            l3 += __shfl_xor_sync(0xffffffff, l3, off);
        }
        if (lane == 0) {
            sm_m[w][0] = mloc[0]; sm_m[w][1] = mloc[1];
            sm_m[w][2] = mloc[2]; sm_m[w][3] = mloc[3];
            sm_l[w][0] = l0; sm_l[w][1] = l1; sm_l[w][2] = l2; sm_l[w][3] = l3;
        }
        __syncwarp();
    }

    // -------- phase C: V stream, one position per iter, all lanes ----------
    {
        u64 acc2[GSZ][2];
#pragma unroll
        for (int g = 0; g < GSZ; g++) { acc2[g][0] = 0ULL; acc2[g][1] = 0ULL; }

#pragma unroll 16
        for (int slot = 0; slot < 64; slot++) {
            const int gl = base + slot;
            const float* vp = vblock + (size_t)slot * NKV * HD;
            if (gl == newpos) vp = &g_vnew[b][kvh][0];
            F4 v4;
            v4.f4 = __ldcs(((const float4*)vp) + lane);
            float4 p4 = ps4[w][slot];            // smem broadcast
            u64 pa = pack2(p4.x, p4.x);
            u64 pb = pack2(p4.y, p4.y);
            u64 pc = pack2(p4.z, p4.z);
            u64 pd = pack2(p4.w, p4.w);
            acc2[0][0] = ffma2(pa, v4.u.lo, acc2[0][0]);
            acc2[0][1] = ffma2(pa, v4.u.hi, acc2[0][1]);
            acc2[1][0] = ffma2(pb, v4.u.lo, acc2[1][0]);
            acc2[1][1] = ffma2(pb, v4.u.hi, acc2[1][1]);
            acc2[2][0] = ffma2(pc, v4.u.lo, acc2[2][0]);
            acc2[2][1] = ffma2(pc, v4.u.hi, acc2[2][1]);
            acc2[3][0] = ffma2(pd, v4.u.lo, acc2[3][0]);
            acc2[3][1] = ffma2(pd, v4.u.hi, acc2[3][1]);
        }
#pragma unroll
        for (int g = 0; g < GSZ; g++) {
            F4 o;
            o.u.lo = acc2[g][0];
            o.u.hi = acc2[g][1];
            ((float4*)&red[w][g][0])[lane] = o.f4;
        }
    }
    __syncthreads();

    // -------- epilogue: flash-merge the 8 warps' partials -> one ----------
    // 256 threads over GSZ*HD = 512 elements: 2 per thread
#pragma unroll
    for (int rep = 0; rep < 2; rep++) {
        int idx = t + rep * 256;
        int g = idx >> 7, d = idx & 127;
        float M = sm_m[0][g];
#pragma unroll
        for (int ww = 1; ww < 8; ww++) M = fmaxf(M, sm_m[ww][g]);
        float o = 0.f;
#pragma unroll
        for (int ww = 0; ww < 8; ww++)
            o += __expf(sm_m[ww][g] - M) * red[ww][g][d];
        g_po[b][kvh][g][s][d] = o;
        if (d == 0) {
            float L = 0.f;
#pragma unroll
            for (int ww = 0; ww < 8; ww++)
                L += __expf(sm_m[ww][g] - M) * sm_l[ww][g];
            g_pm[b][kvh][g][s] = M;
            g_pl[b][kvh][g][s] = L;
        }
    }
}

// ----------------------- combine split partials -----------------------------
// grid: BATCH*NH = 1024 blocks, 128 threads (one per d)
__global__ __launch_bounds__(128) void combine_splits() {
    const int bh = blockIdx.x;
    const int b = bh >> 5, h = bh & 31;
    const int kvh = h >> 2, g = h & 3;
    const int d = threadIdx.x;

    float m = -1e30f;
#pragma unroll
    for (int s = 0; s < NSUB; s++) m = fmaxf(m, g_pm[b][kvh][g][s]);
    float denom = 0.f, o = 0.f;
#pragma unroll
    for (int s = 0; s < NSUB; s++) {
        float e = __expf(g_pm[b][kvh][g][s] - m);
        denom += e * g_pl[b][kvh][g][s];
        o += e * g_po[b][kvh][g][s][d];
    }
    g_attn[b][h * HD + d] = o / denom;
}

// ----------------------- final k-split reduce -------------------------------
__global__ __launch_bounds__(256) void final_reduce(float* __restrict__ out) {
    int e = blockIdx.x * 256 + threadIdx.x;        // over 32*4096
    const float* p = &g_out_part[0][0][0];
    float sum = 0.f;
#pragma unroll
    for (int s = 0; s < KSPLIT; s++) sum += p[(size_t)s * BATCH * DMODEL + e];
    out[e] = sum;
}

// ---------------------------------------------------------------------------
extern "C" void kernel_launch(void* const* d_in, const int* in_sizes, int n_in,
                              void* d_out, int out_size) {
    const float* hid  = (const float*)d_in[0];
    const float* wqkv = (const float*)d_in[1];
    const float* wo   = (const float*)d_in[2];
    const float* kc   = (const float*)d_in[3];
    const float* vc   = (const float*)d_in[4];
    const int*   pos  = (const int*)d_in[5];
    const int*   btab = (const int*)d_in[6];
    const int*   slen = (const int*)d_in[7];
    float* out = (float*)d_out;

    void *p_qkv_part, *p_attn, *p_out_part;
    cudaGetSymbolAddress(&p_qkv_part, g_qkv_part);
    cudaGetSymbolAddress(&p_attn, g_attn);
    cudaGetSymbolAddress(&p_out_part, g_out_part);

    gemm32<<<dim3(QKV_COLS / 128, KSPLIT), 128>>>(hid, wqkv, (float*)p_qkv_part, QKV_COLS);
    rope_reduce<<<(BATCH * 48 * 64) / 256, 256>>>(pos);
    attn_split<<<dim3(SPLITS, NKV, BATCH), 256>>>(kc, vc, btab, slen);
    combine_splits<<<BATCH * NH, 128>>>();
    gemm32<<<dim3(DMODEL / 128, KSPLIT), 128>>>((const float*)p_attn, wo, (float*)p_out_part, DMODEL);
    final_reduce<<<(BATCH * DMODEL) / 256, 256>>>(out);
}